// round 13
// baseline (speedup 1.0000x reference)
#include <cuda_runtime.h>
#include <cuda_bf16.h>
#include <cuda_fp16.h>
#include <cstdint>
#include <math.h>

#define BB 2
#define SS 2048
#define DD 1024
#define HH 16
#define HDIM 64
#define MTOT (BB*SS)      // 4096
#define NN 1024
#define KK 1024

// ---------------- scratch ----------------
__device__ __half g_Qh[(size_t)BB*HH*SS*HDIM];
__device__ __half g_Kh[(size_t)BB*HH*SS*HDIM];
__device__ __half g_Vh[(size_t)BB*HH*SS*HDIM];
__device__ __half g_Xh[(size_t)MTOT*KK];     // x fp16; reused as ctx fp16
__device__ __half g_WT[(size_t)4*NN*KK];     // W^T fp16: Wq,Wk,Wv,Wo stacked
__device__ char g_mask8[(size_t)BB*SS*SS];

#define LOG2E 1.4426950408889634f

__device__ __forceinline__ uint32_t smem_u32(const void* p) {
    uint32_t a;
    asm("{ .reg .u64 t; cvta.to.shared.u64 t, %1; cvt.u32.u64 %0, t; }" : "=r"(a) : "l"(p));
    return a;
}
__device__ __forceinline__ void ldsm_x4(uint32_t* r, uint32_t addr) {
    asm volatile("ldmatrix.sync.aligned.m8n8.x4.shared.b16 {%0,%1,%2,%3}, [%4];"
                 : "=r"(r[0]), "=r"(r[1]), "=r"(r[2]), "=r"(r[3]) : "r"(addr));
}
__device__ __forceinline__ void ldsm_x4_t(uint32_t* r, uint32_t addr) {
    asm volatile("ldmatrix.sync.aligned.m8n8.x4.trans.shared.b16 {%0,%1,%2,%3}, [%4];"
                 : "=r"(r[0]), "=r"(r[1]), "=r"(r[2]), "=r"(r[3]) : "r"(addr));
}
__device__ __forceinline__ void mma16816h(float* c, const uint32_t* a, uint32_t b0, uint32_t b1) {
    asm volatile("mma.sync.aligned.m16n8k16.row.col.f32.f16.f16.f32 "
                 "{%0,%1,%2,%3}, {%4,%5,%6,%7}, {%8,%9}, {%0,%1,%2,%3};"
                 : "+f"(c[0]), "+f"(c[1]), "+f"(c[2]), "+f"(c[3])
                 : "r"(a[0]), "r"(a[1]), "r"(a[2]), "r"(a[3]), "r"(b0), "r"(b1));
}
__device__ __forceinline__ void cpa16(uint32_t s, const void* g) {
    asm volatile("cp.async.cg.shared.global [%0], [%1], 16;" :: "r"(s), "l"(g));
}
#define CPA_COMMIT() asm volatile("cp.async.commit_group;" ::: "memory")
#define CPA_WAIT1()  asm volatile("cp.async.wait_group 1;" ::: "memory")
#define CPA_WAIT0()  asm volatile("cp.async.wait_group 0;" ::: "memory")

__device__ __forceinline__ uint32_t packh(float lo, float hi) {
    __half2 h = __floats2half2_rn(lo, hi);
    return *reinterpret_cast<uint32_t*>(&h);
}
// MUFU.EX2 via inline PTX (ex2.approx); -1e9 flushes to 0.
__device__ __forceinline__ float ex2f(float x) {
    float r;
    asm("ex2.approx.ftz.f32 %0, %1;" : "=f"(r) : "f"(x));
    return r;
}

// ================= prep kernels =================
__global__ __launch_bounds__(256) void convx16_kernel(const float4* __restrict__ X,
                                                      __half* __restrict__ H)
{
    size_t i = (size_t)blockIdx.x * 256 + threadIdx.x;
    float4 v = X[i];
    __half2* H2 = (__half2*)H;
    H2[2*i]   = __floats2half2_rn(v.x, v.y);
    H2[2*i+1] = __floats2half2_rn(v.z, v.w);
}

__global__ __launch_bounds__(256) void convW16_kernel(const float* __restrict__ W0,
                                                      const float* __restrict__ W1,
                                                      const float* __restrict__ W2,
                                                      const float* __restrict__ W3,
                                                      __half* __restrict__ T)
{
    __shared__ float t[32][33];
    const int z = blockIdx.z;
    const float* W = (z == 0) ? W0 : (z == 1) ? W1 : (z == 2) ? W2 : W3;
    const int n0 = blockIdx.x * 32, k0 = blockIdx.y * 32;
    const int tx = threadIdx.x, ty = threadIdx.y;
#pragma unroll
    for (int r = 0; r < 4; r++)
        t[ty + 8*r][tx] = W[(size_t)(k0 + ty + 8*r) * NN + n0 + tx];
    __syncthreads();
#pragma unroll
    for (int r = 0; r < 4; r++) {
        float v = t[tx][ty + 8*r];
        T[((size_t)(z * NN) + n0 + ty + 8*r) * KK + k0 + tx] = __float2half(v);
    }
}

__global__ __launch_bounds__(256) void mask8_kernel(const int4* __restrict__ m,
                                                    uint32_t* __restrict__ o)
{
    size_t i = (size_t)blockIdx.x * 256 + threadIdx.x;
    int4 v = m[i];
    uint32_t r = (v.x ? 1u : 0u) | (v.y ? 0x100u : 0u) | (v.z ? 0x10000u : 0u) | (v.w ? 0x1000000u : 0u);
    o[i] = r;
}

// ================= fp16 single-product GEMM, 3-stage cp.async ========
// MODE 0: fp32 out row-major (out-proj).
// MODE 1: fused QKV. Q scaled by LOG2E/8; K,V plain. Scatter fp16 [b][h][s][hd].
#define SROW 40
#define GT_BYTES (128 * SROW * 2)     // 10240
#define GSTAGE (2 * GT_BYTES)         // 20480: A, B
#define GSM_BYTES (3 * GSTAGE)        // 61440

template<int MODE>
__global__ __launch_bounds__(256, 2) void gemm16_kernel(
    const __half* __restrict__ A, const __half* __restrict__ B,
    const float* __restrict__ bias0, const float* __restrict__ bias1,
    const float* __restrict__ bias2,
    float* __restrict__ out,
    __half* __restrict__ Q_h, __half* __restrict__ K_h, __half* __restrict__ V_h)
{
    extern __shared__ char gsm[];
    const uint32_t u0 = smem_u32(gsm);

    const int tid = threadIdx.x;
    const int wid = tid >> 5;
    const int l   = tid & 31;
    const int wm  = wid >> 2;
    const int wn  = wid & 3;
    const int m_blk = blockIdx.y * 128;
    const int n_blk = blockIdx.x * 128;

    const uint32_t a_off = (uint32_t)((wm * 64 + (l & 15)) * SROW + (l >> 4) * 8) * 2;
    const uint32_t b_off = (uint32_t)((wn * 32 + (l & 7) + ((l >> 4) << 3)) * SROW
                                      + ((l >> 3) & 1) * 8) * 2;

    float acc[4][4][4];
#pragma unroll
    for (int i = 0; i < 4; i++)
#pragma unroll
        for (int j = 0; j < 4; j++)
#pragma unroll
            for (int k = 0; k < 4; k++) acc[i][j][k] = 0.f;

    const int r0 = tid >> 2, s0 = (tid & 3);
    const int r1 = r0 + 64;
    const uint32_t d0 = (uint32_t)(r0 * SROW + s0 * 8) * 2;
    const uint32_t d1 = (uint32_t)(r1 * SROW + s0 * 8) * 2;

#define G_LOAD(ST, KT) do {                                                     \
        const int kg_ = (KT) * 32;                                              \
        const uint32_t sb_ = u0 + (ST) * GSTAGE;                                \
        const size_t gA0_ = (size_t)(m_blk + r0) * KK + kg_ + s0 * 8;           \
        const size_t gA1_ = (size_t)(m_blk + r1) * KK + kg_ + s0 * 8;           \
        const size_t gB0_ = (size_t)(n_blk + r0) * KK + kg_ + s0 * 8;           \
        const size_t gB1_ = (size_t)(n_blk + r1) * KK + kg_ + s0 * 8;           \
        cpa16(sb_ + 0 * GT_BYTES + d0, A + gA0_);                               \
        cpa16(sb_ + 0 * GT_BYTES + d1, A + gA1_);                               \
        cpa16(sb_ + 1 * GT_BYTES + d0, B + gB0_);                               \
        cpa16(sb_ + 1 * GT_BYTES + d1, B + gB1_);                               \
    } while (0)

    G_LOAD(0, 0); CPA_COMMIT();
    G_LOAD(1, 1); CPA_COMMIT();

    for (int kt = 0; kt < 32; kt++) {
        if (kt < 31) CPA_WAIT1(); else CPA_WAIT0();
        __syncthreads();

        const uint32_t sb = u0 + (kt % 3) * GSTAGE;
        const uint32_t uA = sb, uB = sb + GT_BYTES;

#pragma unroll
        for (int ks = 0; ks < 2; ks++) {
            const uint32_t kb = ks * 32;
            uint32_t bh[2][4];
#pragma unroll
            for (int nip = 0; nip < 2; nip++)
                ldsm_x4(bh[nip], uB + b_off + (uint32_t)(nip * 16 * SROW) * 2 + kb);
#pragma unroll
            for (int mi = 0; mi < 4; mi++) {
                const uint32_t ao = a_off + (uint32_t)(mi * 16 * SROW) * 2 + kb;
                uint32_t ah[4];
                ldsm_x4(ah, uA + ao);
#pragma unroll
                for (int ni = 0; ni < 4; ni++)
                    mma16816h(acc[mi][ni], ah, bh[ni >> 1][(ni & 1) * 2], bh[ni >> 1][(ni & 1) * 2 + 1]);
            }
        }

        if (kt + 2 < 32) { G_LOAD((kt + 2) % 3, kt + 2); CPA_COMMIT(); }
    }

    const int sel = n_blk >> 10;
    const float* bias = (MODE == 0) ? bias0 : (sel == 0 ? bias0 : (sel == 1 ? bias1 : bias2));
    const float qscale = LOG2E * 0.125f;

#pragma unroll
    for (int mi = 0; mi < 4; mi++) {
#pragma unroll
        for (int ni = 0; ni < 4; ni++) {
#pragma unroll
            for (int half = 0; half < 2; half++) {
                const int m = m_blk + wm * 64 + mi * 16 + (l >> 2) + half * 8;
                const int ng = n_blk + wn * 32 + ni * 8 + (l & 3) * 2;
                const int nl = ng & 1023;
                float vx = acc[mi][ni][half * 2 + 0] + bias[nl + 0];
                float vy = acc[mi][ni][half * 2 + 1] + bias[nl + 1];
                if (MODE == 0) {
                    *(float2*)&out[(size_t)m * NN + nl] = make_float2(vx, vy);
                } else {
                    const int b = m >> 11, s = m & 2047;
                    const int h = nl >> 6, hd = nl & 63;
                    const size_t o = ((((size_t)b * HH + h) * SS + s) * HDIM) + hd;
                    if (sel == 0) { vx *= qscale; vy *= qscale; }
                    __half* O = (sel == 0) ? Q_h : (sel == 1 ? K_h : V_h);
                    *(__half2*)&O[o] = __floats2half2_rn(vx, vy);
                }
            }
        }
    }
#undef G_LOAD
}

// ================= fp16 single-product flash attention, fixed-max + ex2 ========
#define SRA 72
#define AT_BYTES 18432                   // 128 rows * SRA * 2B
#define ASTAGE_BYTES (3 * AT_BYTES)      // Kh + Vh + mask = 55296
#define ATT_SMEM (2 * ASTAGE_BYTES)      // 110592

__global__ __launch_bounds__(256) void attn_mma_kernel(
    const char* __restrict__ mask8, const float* __restrict__ cmw,
    const __half* __restrict__ Qh, const __half* __restrict__ Kh,
    const __half* __restrict__ Vh, __half* __restrict__ Oh)
{
    extern __shared__ char smn[];
    const uint32_t u0 = smem_u32(smn);
    __shared__ float s_bias;

    const int tid = threadIdx.x, wid = tid >> 5, l = tid & 31;
    const int q0 = blockIdx.x * 128, h = blockIdx.y, b = blockIdx.z;

    if (tid == 0) {
        float s = 0.f;
        for (int i = 0; i < 9; i++) s += cmw[i];
        s_bias = (s / 9.0f - 8.0f) * LOG2E;   // fixed-max 8 + log2e fold
    }

    const size_t qkvb = ((size_t)(b * HH + h) * SS) * HDIM;

    // ---- Q prologue (stage-0 area, consumed before pipeline) ----
    {
        __half* sQh = (__half*)smn;
#pragma unroll
        for (int it = 0; it < 4; it++) {
            int idx = it * 256 + tid;
            int r = idx >> 3, sg = idx & 7;
            size_t g = qkvb + (size_t)(q0 + r) * HDIM + sg * 8;
            *(uint4*)&sQh[r * SRA + sg * 8] = *(const uint4*)&Qh[g];
        }
    }
    __syncthreads();

    uint32_t qfh[4][4];
    const uint32_t qoff = (uint32_t)((wid * 16 + (l & 15)) * SRA + (l >> 4) * 8) * 2;
#pragma unroll
    for (int kc = 0; kc < 4; kc++)
        ldsm_x4(qfh[kc], u0 + qoff + kc * 32);
    __syncthreads();
    const float mbias = s_bias;

    float sum0 = 0.f, sum1 = 0.f;
    float acc[8][4];
#pragma unroll
    for (int i = 0; i < 8; i++)
#pragma unroll
        for (int j = 0; j < 4; j++) acc[i][j] = 0.f;

    const uint32_t koff = (uint32_t)(((l & 7) + ((l >> 4) << 3)) * SRA + ((l >> 3) & 1) * 8) * 2;
    const uint32_t voff = (uint32_t)((l & 15) * SRA + (l >> 4) * 8) * 2;
    const int rl0 = wid * 16 + (l >> 2);
    const int rl1 = rl0 + 8;

#define A_LOAD(ST, JT) do {                                                        \
        const int j0_ = (JT) * 128;                                                \
        const uint32_t sb_ = u0 + (ST) * ASTAGE_BYTES;                             \
        _Pragma("unroll")                                                          \
        for (int it = 0; it < 4; it++) {                                           \
            int idx = it * 256 + tid;                                              \
            int r = idx >> 3, sg = idx & 7;                                        \
            size_t g = qkvb + (size_t)(j0_ + r) * HDIM + sg * 8;                   \
            uint32_t d = (uint32_t)(r * SRA + sg * 8) * 2;                         \
            cpa16(sb_ + 0 * AT_BYTES + d, Kh + g);                                 \
            cpa16(sb_ + 1 * AT_BYTES + d, Vh + g);                                 \
        }                                                                          \
        _Pragma("unroll")                                                          \
        for (int it = 0; it < 4; it++) {                                           \
            int idx = it * 256 + tid;                                              \
            int r = idx >> 3, c = (idx & 7) * 16;                                  \
            cpa16(sb_ + 2 * AT_BYTES + r * 144 + c,                                \
                  mask8 + ((size_t)b * SS + q0 + r) * SS + j0_ + c);               \
        }                                                                          \
    } while (0)

    A_LOAD(0, 0);
    CPA_COMMIT();

    for (int jt = 0; jt < 16; jt++) {
        if (jt + 1 < 16) {
            A_LOAD((jt + 1) & 1, jt + 1);
            CPA_COMMIT();
            CPA_WAIT1();
        } else {
            CPA_WAIT0();
        }
        __syncthreads();

        const uint32_t sb = u0 + (jt & 1) * ASTAGE_BYTES;
        const uint32_t uKh = sb, uVh = sb + AT_BYTES;
        const char* sMask = smn + (jt & 1) * ASTAGE_BYTES + 2 * AT_BYTES;

        // ---- scores: Qh . Kh (single product) ----
        float sc[16][4];
#pragma unroll
        for (int i = 0; i < 16; i++)
#pragma unroll
            for (int j = 0; j < 4; j++) sc[i][j] = 0.f;

#pragma unroll
        for (int kc = 0; kc < 4; kc++) {
#pragma unroll
            for (int nbp = 0; nbp < 4; nbp++) {
                uint32_t bh0[4], bh1[4];
                uint32_t bo0 = koff + (uint32_t)((2*nbp    ) * 16 * SRA) * 2 + kc * 32;
                uint32_t bo1 = koff + (uint32_t)((2*nbp + 1) * 16 * SRA) * 2 + kc * 32;
                ldsm_x4(bh0, uKh + bo0);
                ldsm_x4(bh1, uKh + bo1);
                mma16816h(sc[4*nbp + 0], qfh[kc], bh0[0], bh0[1]);
                mma16816h(sc[4*nbp + 1], qfh[kc], bh0[2], bh0[3]);
                mma16816h(sc[4*nbp + 2], qfh[kc], bh1[0], bh1[1]);
                mma16816h(sc[4*nbp + 3], qfh[kc], bh1[2], bh1[3]);
            }
        }

        // ---- bias + mask + ex2 (MUFU), lane-local sums ----
#pragma unroll
        for (int nf = 0; nf < 16; nf++) {
            int c = nf * 8 + (l & 3) * 2;
            char2 ma = *(char2*)&sMask[rl0 * 144 + c];
            char2 mb = *(char2*)&sMask[rl1 * 144 + c];
            float p0 = ex2f(ma.x ? (sc[nf][0] + mbias) : -1e9f);
            float p1 = ex2f(ma.y ? (sc[nf][1] + mbias) : -1e9f);
            float p2 = ex2f(mb.x ? (sc[nf][2] + mbias) : -1e9f);
            float p3 = ex2f(mb.y ? (sc[nf][3] + mbias) : -1e9f);
            sc[nf][0] = p0; sc[nf][1] = p1; sc[nf][2] = p2; sc[nf][3] = p3;
            sum0 += p0 + p1;
            sum1 += p2 + p3;
        }

        // ---- ctx += Ph . Vh (single product) ----
#pragma unroll
        for (int kc = 0; kc < 8; kc++) {
            uint32_t ah[4];
            ah[0] = packh(sc[2*kc][0], sc[2*kc][1]);
            ah[1] = packh(sc[2*kc][2], sc[2*kc][3]);
            ah[2] = packh(sc[2*kc+1][0], sc[2*kc+1][1]);
            ah[3] = packh(sc[2*kc+1][2], sc[2*kc+1][3]);
            const uint32_t vb = voff + (uint32_t)(kc * 16 * SRA) * 2;
#pragma unroll
            for (int dbp = 0; dbp < 2; dbp++) {
                uint32_t vh0[4], vh1[4];
                ldsm_x4_t(vh0, uVh + vb + (2*dbp    ) * 32);
                ldsm_x4_t(vh1, uVh + vb + (2*dbp + 1) * 32);
                mma16816h(acc[4*dbp + 0], ah, vh0[0], vh0[1]);
                mma16816h(acc[4*dbp + 1], ah, vh0[2], vh0[3]);
                mma16816h(acc[4*dbp + 2], ah, vh1[0], vh1[1]);
                mma16816h(acc[4*dbp + 3], ah, vh1[2], vh1[3]);
            }
        }
        __syncthreads();
    }

    // ---- epilogue: reduce sums over lane group, normalize, fp16 ctx out ----
    sum0 += __shfl_xor_sync(0xffffffffu, sum0, 1);
    sum0 += __shfl_xor_sync(0xffffffffu, sum0, 2);
    sum1 += __shfl_xor_sync(0xffffffffu, sum1, 1);
    sum1 += __shfl_xor_sync(0xffffffffu, sum1, 2);
    const float inv0 = 1.0f / sum0, inv1 = 1.0f / sum1;
    const size_t rg0 = (size_t)b * SS + q0 + wid * 16 + (l >> 2);
    const size_t rg1 = rg0 + 8;
#pragma unroll
    for (int nf = 0; nf < 8; nf++) {
        const int col = h * 64 + nf * 8 + (l & 3) * 2;
        *(__half2*)&Oh[rg0 * DD + col] = __floats2half2_rn(acc[nf][0] * inv0, acc[nf][1] * inv0);
        *(__half2*)&Oh[rg1 * DD + col] = __floats2half2_rn(acc[nf][2] * inv1, acc[nf][3] * inv1);
    }
#undef A_LOAD
}

// ---------------- launch ----------------
extern "C" void kernel_launch(void* const* d_in, const int* in_sizes, int n_in,
                              void* d_out, int out_size)
{
    const float* x   = (const float*)d_in[0];
    const float* Wq  = (const float*)d_in[1];
    const float* bq  = (const float*)d_in[2];
    const float* Wk  = (const float*)d_in[3];
    const float* bk  = (const float*)d_in[4];
    const float* Wv  = (const float*)d_in[5];
    const float* bv  = (const float*)d_in[6];
    const float* Wo  = (const float*)d_in[7];
    const float* bo  = (const float*)d_in[8];
    const float* cmw = (const float*)d_in[9];
    const int*  mask = (const int*)d_in[10];
    float* out = (float*)d_out;

    void *pQh, *pKh, *pVh, *pXh, *pWT, *pM8;
    cudaGetSymbolAddress(&pQh, g_Qh);
    cudaGetSymbolAddress(&pKh, g_Kh);
    cudaGetSymbolAddress(&pVh, g_Vh);
    cudaGetSymbolAddress(&pXh, g_Xh);
    cudaGetSymbolAddress(&pWT, g_WT);
    cudaGetSymbolAddress(&pM8, g_mask8);
    __half* Xhp = (__half*)pXh;
    __half* WTp = (__half*)pWT;

    static int s_init = 0;
    if (!s_init) {
        cudaFuncSetAttribute(attn_mma_kernel, cudaFuncAttributeMaxDynamicSharedMemorySize, ATT_SMEM);
        cudaFuncSetAttribute(gemm16_kernel<0>, cudaFuncAttributeMaxDynamicSharedMemorySize, GSM_BYTES);
        cudaFuncSetAttribute(gemm16_kernel<1>, cudaFuncAttributeMaxDynamicSharedMemorySize, GSM_BYTES);
        s_init = 1;
    }

    mask8_kernel<<<(BB * SS * SS) / (4 * 256), 256>>>((const int4*)mask, (uint32_t*)pM8);
    convx16_kernel<<<(MTOT * KK) / (256 * 4), 256>>>((const float4*)x, Xhp);
    convW16_kernel<<<dim3(NN / 32, KK / 32, 4), dim3(32, 8)>>>(Wq, Wk, Wv, Wo, WTp);

    // fused QKV projection: N = 3072
    gemm16_kernel<1><<<dim3(3 * NN / 128, MTOT / 128), 256, GSM_BYTES>>>(
        Xhp, WTp, bq, bk, bv, nullptr,
        (__half*)pQh, (__half*)pKh, (__half*)pVh);

    // attention (writes ctx into Xh as fp16)
    attn_mma_kernel<<<dim3(SS / 128, HH, BB), 256, ATT_SMEM>>>(
        (const char*)pM8, cmw,
        (const __half*)pQh, (const __half*)pKh, (const __half*)pVh, Xhp);

    // out-projection
    gemm16_kernel<0><<<dim3(NN / 128, MTOT / 128), 256, GSM_BYTES>>>(
        Xhp, WTp + (size_t)3 * NN * KK, bo, nullptr, nullptr, out,
        nullptr, nullptr, nullptr);
}

// round 14
// speedup vs baseline: 1.8136x; 1.8136x over previous
#include <cuda_runtime.h>
#include <cuda_bf16.h>
#include <cuda_fp16.h>
#include <cstdint>
#include <math.h>

#define BB 2
#define SS 2048
#define DD 1024
#define HH 16
#define HDIM 64
#define MTOT (BB*SS)      // 4096
#define NN 1024
#define KK 1024

// ---------------- scratch ----------------
__device__ __half g_Qh[(size_t)BB*HH*SS*HDIM];
__device__ __half g_Kh[(size_t)BB*HH*SS*HDIM];
__device__ __half g_Vh[(size_t)BB*HH*SS*HDIM];
__device__ __half g_Xh[(size_t)MTOT*KK];     // x fp16; reused as ctx fp16
__device__ __half g_WT[(size_t)4*NN*KK];     // W^T fp16: Wq,Wk,Wv,Wo stacked
__device__ char g_mask8[(size_t)BB*SS*SS];

#define LOG2E 1.4426950408889634f

__device__ __forceinline__ uint32_t smem_u32(const void* p) {
    uint32_t a;
    asm("{ .reg .u64 t; cvta.to.shared.u64 t, %1; cvt.u32.u64 %0, t; }" : "=r"(a) : "l"(p));
    return a;
}
__device__ __forceinline__ void ldsm_x4(uint32_t* r, uint32_t addr) {
    asm volatile("ldmatrix.sync.aligned.m8n8.x4.shared.b16 {%0,%1,%2,%3}, [%4];"
                 : "=r"(r[0]), "=r"(r[1]), "=r"(r[2]), "=r"(r[3]) : "r"(addr));
}
__device__ __forceinline__ void ldsm_x4_t(uint32_t* r, uint32_t addr) {
    asm volatile("ldmatrix.sync.aligned.m8n8.x4.trans.shared.b16 {%0,%1,%2,%3}, [%4];"
                 : "=r"(r[0]), "=r"(r[1]), "=r"(r[2]), "=r"(r[3]) : "r"(addr));
}
__device__ __forceinline__ void mma16816h(float* c, const uint32_t* a, uint32_t b0, uint32_t b1) {
    asm volatile("mma.sync.aligned.m16n8k16.row.col.f32.f16.f16.f32 "
                 "{%0,%1,%2,%3}, {%4,%5,%6,%7}, {%8,%9}, {%0,%1,%2,%3};"
                 : "+f"(c[0]), "+f"(c[1]), "+f"(c[2]), "+f"(c[3])
                 : "r"(a[0]), "r"(a[1]), "r"(a[2]), "r"(a[3]), "r"(b0), "r"(b1));
}
__device__ __forceinline__ void cpa16(uint32_t s, const void* g) {
    asm volatile("cp.async.cg.shared.global [%0], [%1], 16;" :: "r"(s), "l"(g));
}
#define CPA_COMMIT() asm volatile("cp.async.commit_group;" ::: "memory")
#define CPA_WAIT1()  asm volatile("cp.async.wait_group 1;" ::: "memory")
#define CPA_WAIT0()  asm volatile("cp.async.wait_group 0;" ::: "memory")

__device__ __forceinline__ uint32_t packh(float lo, float hi) {
    __half2 h = __floats2half2_rn(lo, hi);
    return *reinterpret_cast<uint32_t*>(&h);
}
// MUFU.EX2 via inline PTX (ex2.approx); -1e9 flushes to 0.
__device__ __forceinline__ float ex2f(float x) {
    float r;
    asm("ex2.approx.ftz.f32 %0, %1;" : "=f"(r) : "f"(x));
    return r;
}

// ================= prep kernels =================
__global__ __launch_bounds__(256) void convx16_kernel(const float4* __restrict__ X,
                                                      __half* __restrict__ H)
{
    size_t i = (size_t)blockIdx.x * 256 + threadIdx.x;
    float4 v = X[i];
    __half2* H2 = (__half2*)H;
    H2[2*i]   = __floats2half2_rn(v.x, v.y);
    H2[2*i+1] = __floats2half2_rn(v.z, v.w);
}

__global__ __launch_bounds__(256) void convW16_kernel(const float* __restrict__ W0,
                                                      const float* __restrict__ W1,
                                                      const float* __restrict__ W2,
                                                      const float* __restrict__ W3,
                                                      __half* __restrict__ T)
{
    __shared__ float t[32][33];
    const int z = blockIdx.z;
    const float* W = (z == 0) ? W0 : (z == 1) ? W1 : (z == 2) ? W2 : W3;
    const int n0 = blockIdx.x * 32, k0 = blockIdx.y * 32;
    const int tx = threadIdx.x, ty = threadIdx.y;
#pragma unroll
    for (int r = 0; r < 4; r++)
        t[ty + 8*r][tx] = W[(size_t)(k0 + ty + 8*r) * NN + n0 + tx];
    __syncthreads();
#pragma unroll
    for (int r = 0; r < 4; r++) {
        float v = t[tx][ty + 8*r];
        T[((size_t)(z * NN) + n0 + ty + 8*r) * KK + k0 + tx] = __float2half(v);
    }
}

__global__ __launch_bounds__(256) void mask8_kernel(const int4* __restrict__ m,
                                                    uint32_t* __restrict__ o)
{
    size_t i = (size_t)blockIdx.x * 256 + threadIdx.x;
    int4 v = m[i];
    uint32_t r = (v.x ? 1u : 0u) | (v.y ? 0x100u : 0u) | (v.z ? 0x10000u : 0u) | (v.w ? 0x1000000u : 0u);
    o[i] = r;
}

// ================= fp16 single-product GEMM, BK=64, 3-stage cp.async ========
// MODE 0: fp32 out row-major (out-proj).
// MODE 1: fused QKV. Q scaled by LOG2E/8; K,V plain. Scatter fp16 [b][h][s][hd].
#define SROW 72                        // 64 data cols padded to 72 (144B rows)
#define GT_BYTES (128 * SROW * 2)      // 18432
#define GSTAGE (2 * GT_BYTES)          // 36864: A, B
#define GSM_BYTES (3 * GSTAGE)         // 110592

template<int MODE>
__global__ __launch_bounds__(256, 2) void gemm16_kernel(
    const __half* __restrict__ A, const __half* __restrict__ B,
    const float* __restrict__ bias0, const float* __restrict__ bias1,
    const float* __restrict__ bias2,
    float* __restrict__ out,
    __half* __restrict__ Q_h, __half* __restrict__ K_h, __half* __restrict__ V_h)
{
    extern __shared__ char gsm[];
    const uint32_t u0 = smem_u32(gsm);

    const int tid = threadIdx.x;
    const int wid = tid >> 5;
    const int l   = tid & 31;
    const int wm  = wid >> 2;
    const int wn  = wid & 3;
    const int m_blk = blockIdx.y * 128;
    const int n_blk = blockIdx.x * 128;

    const uint32_t a_off = (uint32_t)((wm * 64 + (l & 15)) * SROW + (l >> 4) * 8) * 2;
    const uint32_t b_off = (uint32_t)((wn * 32 + (l & 7) + ((l >> 4) << 3)) * SROW
                                      + ((l >> 3) & 1) * 8) * 2;

    float acc[4][4][4];
#pragma unroll
    for (int i = 0; i < 4; i++)
#pragma unroll
        for (int j = 0; j < 4; j++)
#pragma unroll
            for (int k = 0; k < 4; k++) acc[i][j][k] = 0.f;

    // global loads: 128x64 fp16 tile = 1024 x 16B; 256 threads x 4 chunks each
    const int gr = tid >> 3;           // 0..31 base row
    const int gs = tid & 7;            // 0..7 column segment (8 fp16 each)

#define G_LOAD(ST, KT) do {                                                     \
        const int kg_ = (KT) * 64;                                              \
        const uint32_t sb_ = u0 + (ST) * GSTAGE;                                \
        _Pragma("unroll")                                                       \
        for (int it = 0; it < 4; it++) {                                        \
            const int r_ = gr + it * 32;                                        \
            const uint32_t d_ = (uint32_t)(r_ * SROW + gs * 8) * 2;             \
            const size_t gA_ = (size_t)(m_blk + r_) * KK + kg_ + gs * 8;        \
            const size_t gB_ = (size_t)(n_blk + r_) * KK + kg_ + gs * 8;        \
            cpa16(sb_ + 0 * GT_BYTES + d_, A + gA_);                            \
            cpa16(sb_ + 1 * GT_BYTES + d_, B + gB_);                            \
        }                                                                       \
    } while (0)

    G_LOAD(0, 0); CPA_COMMIT();
    G_LOAD(1, 1); CPA_COMMIT();

    for (int kt = 0; kt < 16; kt++) {
        if (kt < 15) CPA_WAIT1(); else CPA_WAIT0();
        __syncthreads();

        const uint32_t sb = u0 + (kt % 3) * GSTAGE;
        const uint32_t uA = sb, uB = sb + GT_BYTES;

#pragma unroll
        for (int ks = 0; ks < 4; ks++) {
            const uint32_t kb = ks * 32;
            uint32_t bh[2][4];
#pragma unroll
            for (int nip = 0; nip < 2; nip++)
                ldsm_x4(bh[nip], uB + b_off + (uint32_t)(nip * 16 * SROW) * 2 + kb);
#pragma unroll
            for (int mi = 0; mi < 4; mi++) {
                const uint32_t ao = a_off + (uint32_t)(mi * 16 * SROW) * 2 + kb;
                uint32_t ah[4];
                ldsm_x4(ah, uA + ao);
#pragma unroll
                for (int ni = 0; ni < 4; ni++)
                    mma16816h(acc[mi][ni], ah, bh[ni >> 1][(ni & 1) * 2], bh[ni >> 1][(ni & 1) * 2 + 1]);
            }
        }

        if (kt + 2 < 16) { G_LOAD((kt + 2) % 3, kt + 2); CPA_COMMIT(); }
    }

    const int sel = n_blk >> 10;
    const float* bias = (MODE == 0) ? bias0 : (sel == 0 ? bias0 : (sel == 1 ? bias1 : bias2));
    const float qscale = LOG2E * 0.125f;

#pragma unroll
    for (int mi = 0; mi < 4; mi++) {
#pragma unroll
        for (int ni = 0; ni < 4; ni++) {
#pragma unroll
            for (int half = 0; half < 2; half++) {
                const int m = m_blk + wm * 64 + mi * 16 + (l >> 2) + half * 8;
                const int ng = n_blk + wn * 32 + ni * 8 + (l & 3) * 2;
                const int nl = ng & 1023;
                float vx = acc[mi][ni][half * 2 + 0] + bias[nl + 0];
                float vy = acc[mi][ni][half * 2 + 1] + bias[nl + 1];
                if (MODE == 0) {
                    *(float2*)&out[(size_t)m * NN + nl] = make_float2(vx, vy);
                } else {
                    const int b = m >> 11, s = m & 2047;
                    const int h = nl >> 6, hd = nl & 63;
                    const size_t o = ((((size_t)b * HH + h) * SS + s) * HDIM) + hd;
                    if (sel == 0) { vx *= qscale; vy *= qscale; }
                    __half* O = (sel == 0) ? Q_h : (sel == 1 ? K_h : V_h);
                    *(__half2*)&O[o] = __floats2half2_rn(vx, vy);
                }
            }
        }
    }
#undef G_LOAD
}

// ================= fp16 single-product flash attention, fixed-max + ex2 ========
#define SRA 72
#define AT_BYTES 18432                   // 128 rows * SRA * 2B
#define ASTAGE_BYTES (3 * AT_BYTES)      // Kh + Vh + mask = 55296
#define ATT_SMEM (2 * ASTAGE_BYTES)      // 110592

__global__ __launch_bounds__(256) void attn_mma_kernel(
    const char* __restrict__ mask8, const float* __restrict__ cmw,
    const __half* __restrict__ Qh, const __half* __restrict__ Kh,
    const __half* __restrict__ Vh, __half* __restrict__ Oh)
{
    extern __shared__ char smn[];
    const uint32_t u0 = smem_u32(smn);
    __shared__ float s_bias;

    const int tid = threadIdx.x, wid = tid >> 5, l = tid & 31;
    const int q0 = blockIdx.x * 128, h = blockIdx.y, b = blockIdx.z;

    if (tid == 0) {
        float s = 0.f;
        for (int i = 0; i < 9; i++) s += cmw[i];
        s_bias = (s / 9.0f - 8.0f) * LOG2E;   // fixed-max 8 + log2e fold
    }

    const size_t qkvb = ((size_t)(b * HH + h) * SS) * HDIM;

    // ---- Q prologue (stage-0 area, consumed before pipeline) ----
    {
        __half* sQh = (__half*)smn;
#pragma unroll
        for (int it = 0; it < 4; it++) {
            int idx = it * 256 + tid;
            int r = idx >> 3, sg = idx & 7;
            size_t g = qkvb + (size_t)(q0 + r) * HDIM + sg * 8;
            *(uint4*)&sQh[r * SRA + sg * 8] = *(const uint4*)&Qh[g];
        }
    }
    __syncthreads();

    uint32_t qfh[4][4];
    const uint32_t qoff = (uint32_t)((wid * 16 + (l & 15)) * SRA + (l >> 4) * 8) * 2;
#pragma unroll
    for (int kc = 0; kc < 4; kc++)
        ldsm_x4(qfh[kc], u0 + qoff + kc * 32);
    __syncthreads();
    const float mbias = s_bias;

    float sum0 = 0.f, sum1 = 0.f;
    float acc[8][4];
#pragma unroll
    for (int i = 0; i < 8; i++)
#pragma unroll
        for (int j = 0; j < 4; j++) acc[i][j] = 0.f;

    const uint32_t koff = (uint32_t)(((l & 7) + ((l >> 4) << 3)) * SRA + ((l >> 3) & 1) * 8) * 2;
    const uint32_t voff = (uint32_t)((l & 15) * SRA + (l >> 4) * 8) * 2;
    const int rl0 = wid * 16 + (l >> 2);
    const int rl1 = rl0 + 8;

#define A_LOAD(ST, JT) do {                                                        \
        const int j0_ = (JT) * 128;                                                \
        const uint32_t sb_ = u0 + (ST) * ASTAGE_BYTES;                             \
        _Pragma("unroll")                                                          \
        for (int it = 0; it < 4; it++) {                                           \
            int idx = it * 256 + tid;                                              \
            int r = idx >> 3, sg = idx & 7;                                        \
            size_t g = qkvb + (size_t)(j0_ + r) * HDIM + sg * 8;                   \
            uint32_t d = (uint32_t)(r * SRA + sg * 8) * 2;                         \
            cpa16(sb_ + 0 * AT_BYTES + d, Kh + g);                                 \
            cpa16(sb_ + 1 * AT_BYTES + d, Vh + g);                                 \
        }                                                                          \
        _Pragma("unroll")                                                          \
        for (int it = 0; it < 4; it++) {                                           \
            int idx = it * 256 + tid;                                              \
            int r = idx >> 3, c = (idx & 7) * 16;                                  \
            cpa16(sb_ + 2 * AT_BYTES + r * 144 + c,                                \
                  mask8 + ((size_t)b * SS + q0 + r) * SS + j0_ + c);               \
        }                                                                          \
    } while (0)

    A_LOAD(0, 0);
    CPA_COMMIT();

    for (int jt = 0; jt < 16; jt++) {
        if (jt + 1 < 16) {
            A_LOAD((jt + 1) & 1, jt + 1);
            CPA_COMMIT();
            CPA_WAIT1();
        } else {
            CPA_WAIT0();
        }
        __syncthreads();

        const uint32_t sb = u0 + (jt & 1) * ASTAGE_BYTES;
        const uint32_t uKh = sb, uVh = sb + AT_BYTES;
        const char* sMask = smn + (jt & 1) * ASTAGE_BYTES + 2 * AT_BYTES;

        // ---- scores: Qh . Kh (single product) ----
        float sc[16][4];
#pragma unroll
        for (int i = 0; i < 16; i++)
#pragma unroll
            for (int j = 0; j < 4; j++) sc[i][j] = 0.f;

#pragma unroll
        for (int kc = 0; kc < 4; kc++) {
#pragma unroll
            for (int nbp = 0; nbp < 4; nbp++) {
                uint32_t bh0[4], bh1[4];
                uint32_t bo0 = koff + (uint32_t)((2*nbp    ) * 16 * SRA) * 2 + kc * 32;
                uint32_t bo1 = koff + (uint32_t)((2*nbp + 1) * 16 * SRA) * 2 + kc * 32;
                ldsm_x4(bh0, uKh + bo0);
                ldsm_x4(bh1, uKh + bo1);
                mma16816h(sc[4*nbp + 0], qfh[kc], bh0[0], bh0[1]);
                mma16816h(sc[4*nbp + 1], qfh[kc], bh0[2], bh0[3]);
                mma16816h(sc[4*nbp + 2], qfh[kc], bh1[0], bh1[1]);
                mma16816h(sc[4*nbp + 3], qfh[kc], bh1[2], bh1[3]);
            }
        }

        // ---- bias + mask + ex2 (MUFU), lane-local sums ----
#pragma unroll
        for (int nf = 0; nf < 16; nf++) {
            int c = nf * 8 + (l & 3) * 2;
            char2 ma = *(char2*)&sMask[rl0 * 144 + c];
            char2 mb = *(char2*)&sMask[rl1 * 144 + c];
            float p0 = ex2f(ma.x ? (sc[nf][0] + mbias) : -1e9f);
            float p1 = ex2f(ma.y ? (sc[nf][1] + mbias) : -1e9f);
            float p2 = ex2f(mb.x ? (sc[nf][2] + mbias) : -1e9f);
            float p3 = ex2f(mb.y ? (sc[nf][3] + mbias) : -1e9f);
            sc[nf][0] = p0; sc[nf][1] = p1; sc[nf][2] = p2; sc[nf][3] = p3;
            sum0 += p0 + p1;
            sum1 += p2 + p3;
        }

        // ---- ctx += Ph . Vh (single product) ----
#pragma unroll
        for (int kc = 0; kc < 8; kc++) {
            uint32_t ah[4];
            ah[0] = packh(sc[2*kc][0], sc[2*kc][1]);
            ah[1] = packh(sc[2*kc][2], sc[2*kc][3]);
            ah[2] = packh(sc[2*kc+1][0], sc[2*kc+1][1]);
            ah[3] = packh(sc[2*kc+1][2], sc[2*kc+1][3]);
            const uint32_t vb = voff + (uint32_t)(kc * 16 * SRA) * 2;
#pragma unroll
            for (int dbp = 0; dbp < 2; dbp++) {
                uint32_t vh0[4], vh1[4];
                ldsm_x4_t(vh0, uVh + vb + (2*dbp    ) * 32);
                ldsm_x4_t(vh1, uVh + vb + (2*dbp + 1) * 32);
                mma16816h(acc[4*dbp + 0], ah, vh0[0], vh0[1]);
                mma16816h(acc[4*dbp + 1], ah, vh0[2], vh0[3]);
                mma16816h(acc[4*dbp + 2], ah, vh1[0], vh1[1]);
                mma16816h(acc[4*dbp + 3], ah, vh1[2], vh1[3]);
            }
        }
        __syncthreads();
    }

    // ---- epilogue: reduce sums over lane group, normalize, fp16 ctx out ----
    sum0 += __shfl_xor_sync(0xffffffffu, sum0, 1);
    sum0 += __shfl_xor_sync(0xffffffffu, sum0, 2);
    sum1 += __shfl_xor_sync(0xffffffffu, sum1, 1);
    sum1 += __shfl_xor_sync(0xffffffffu, sum1, 2);
    const float inv0 = 1.0f / sum0, inv1 = 1.0f / sum1;
    const size_t rg0 = (size_t)b * SS + q0 + wid * 16 + (l >> 2);
    const size_t rg1 = rg0 + 8;
#pragma unroll
    for (int nf = 0; nf < 8; nf++) {
        const int col = h * 64 + nf * 8 + (l & 3) * 2;
        *(__half2*)&Oh[rg0 * DD + col] = __floats2half2_rn(acc[nf][0] * inv0, acc[nf][1] * inv0);
        *(__half2*)&Oh[rg1 * DD + col] = __floats2half2_rn(acc[nf][2] * inv1, acc[nf][3] * inv1);
    }
#undef A_LOAD
}

// ---------------- launch ----------------
extern "C" void kernel_launch(void* const* d_in, const int* in_sizes, int n_in,
                              void* d_out, int out_size)
{
    const float* x   = (const float*)d_in[0];
    const float* Wq  = (const float*)d_in[1];
    const float* bq  = (const float*)d_in[2];
    const float* Wk  = (const float*)d_in[3];
    const float* bk  = (const float*)d_in[4];
    const float* Wv  = (const float*)d_in[5];
    const float* bv  = (const float*)d_in[6];
    const float* Wo  = (const float*)d_in[7];
    const float* bo  = (const float*)d_in[8];
    const float* cmw = (const float*)d_in[9];
    const int*  mask = (const int*)d_in[10];
    float* out = (float*)d_out;

    void *pQh, *pKh, *pVh, *pXh, *pWT, *pM8;
    cudaGetSymbolAddress(&pQh, g_Qh);
    cudaGetSymbolAddress(&pKh, g_Kh);
    cudaGetSymbolAddress(&pVh, g_Vh);
    cudaGetSymbolAddress(&pXh, g_Xh);
    cudaGetSymbolAddress(&pWT, g_WT);
    cudaGetSymbolAddress(&pM8, g_mask8);
    __half* Xhp = (__half*)pXh;
    __half* WTp = (__half*)pWT;

    static int s_init = 0;
    if (!s_init) {
        cudaFuncSetAttribute(attn_mma_kernel, cudaFuncAttributeMaxDynamicSharedMemorySize, ATT_SMEM);
        cudaFuncSetAttribute(gemm16_kernel<0>, cudaFuncAttributeMaxDynamicSharedMemorySize, GSM_BYTES);
        cudaFuncSetAttribute(gemm16_kernel<1>, cudaFuncAttributeMaxDynamicSharedMemorySize, GSM_BYTES);
        s_init = 1;
    }

    mask8_kernel<<<(BB * SS * SS) / (4 * 256), 256>>>((const int4*)mask, (uint32_t*)pM8);
    convx16_kernel<<<(MTOT * KK) / (256 * 4), 256>>>((const float4*)x, Xhp);
    convW16_kernel<<<dim3(NN / 32, KK / 32, 4), dim3(32, 8)>>>(Wq, Wk, Wv, Wo, WTp);

    // fused QKV projection: N = 3072
    gemm16_kernel<1><<<dim3(3 * NN / 128, MTOT / 128), 256, GSM_BYTES>>>(
        Xhp, WTp, bq, bk, bv, nullptr,
        (__half*)pQh, (__half*)pKh, (__half*)pVh);

    // attention (writes ctx into Xh as fp16)
    attn_mma_kernel<<<dim3(SS / 128, HH, BB), 256, ATT_SMEM>>>(
        (const char*)pM8, cmw,
        (const __half*)pQh, (const __half*)pKh, (const __half*)pVh, Xhp);

    // out-projection
    gemm16_kernel<0><<<dim3(NN / 128, MTOT / 128), 256, GSM_BYTES>>>(
        Xhp, WTp + (size_t)3 * NN * KK, bo, nullptr, nullptr, out,
        nullptr, nullptr, nullptr);
}